// round 9
// baseline (speedup 1.0000x reference)
#include <cuda_runtime.h>
#include <cuda_fp16.h>
#include <cstdint>

#define NN 4000
#define SS 64
#define TT 12
#define K3S 192   // 3*SS
#define NCH 125   // 4000 / 32 n-chunks

// ------------------------- device scratch (no allocs) -------------------------
__device__ __align__(16) float g_h[NN * SS];
__device__ __align__(16) float g_act[(size_t)TT * NN * SS];
__device__ __align__(16) float g_aw[NN * K3S];
// chunk-blocked E: [t][ci][m][32] halves
__device__ __align__(16) __half g_eB_hi[(size_t)TT * NCH * NN * 32];
__device__ __align__(16) __half g_eB_lo[(size_t)TT * NCH * NN * 32];
// chunk-blocked hT: [ci][s][32]
__device__ __align__(16) __half g_hB_hi[NCH * SS * 32];
__device__ __align__(16) __half g_hB_lo[NCH * SS * 32];

// ------------------------- helpers -------------------------
__device__ __forceinline__ void ffma2(unsigned long long& d,
                                      unsigned long long a,
                                      unsigned long long b) {
    asm volatile("fma.rn.f32x2 %0, %1, %2, %0;" : "+l"(d) : "l"(a), "l"(b));
}
__device__ __forceinline__ unsigned long long pack2(float x) {
    unsigned long long r;
    asm("mov.b64 %0, {%1, %1};" : "=l"(r) : "r"(__float_as_uint(x)));
    return r;
}
__device__ __forceinline__ float lo32(unsigned long long v) {
    return __uint_as_float((unsigned)(v & 0xffffffffull));
}
__device__ __forceinline__ float hi32(unsigned long long v) {
    return __uint_as_float((unsigned)(v >> 32));
}
__device__ __forceinline__ uint32_t smem_u32(const void* p) {
    uint32_t a;
    asm("{ .reg .u64 t; cvta.to.shared.u64 t, %1; cvt.u32.u64 %0, t; }" : "=r"(a) : "l"(p));
    return a;
}
__device__ __forceinline__ void cp16(uint32_t dst, const void* src, int bytes) {
    asm volatile("cp.async.cg.shared.global [%0], [%1], 16, %2;" :: "r"(dst), "l"(src), "r"(bytes));
}
__device__ __forceinline__ void cp_commit() { asm volatile("cp.async.commit_group;"); }
__device__ __forceinline__ void cp_wait1()  { asm volatile("cp.async.wait_group 1;"); }
__device__ __forceinline__ void cp_wait0()  { asm volatile("cp.async.wait_group 0;"); }

__device__ __forceinline__ void ldsm4(uint32_t& r0, uint32_t& r1, uint32_t& r2, uint32_t& r3,
                                      uint32_t addr) {
    asm volatile("ldmatrix.sync.aligned.m8n8.x4.shared.b16 {%0,%1,%2,%3}, [%4];"
                 : "=r"(r0), "=r"(r1), "=r"(r2), "=r"(r3) : "r"(addr));
}
__device__ __forceinline__ void mma16816(float* c, const uint32_t* a, const uint32_t* b) {
    asm volatile("mma.sync.aligned.m16n8k16.row.col.f32.f16.f16.f32 "
                 "{%0,%1,%2,%3}, {%4,%5,%6,%7}, {%8,%9}, {%0,%1,%2,%3};"
                 : "+f"(c[0]), "+f"(c[1]), "+f"(c[2]), "+f"(c[3])
                 : "r"(a[0]), "r"(a[1]), "r"(a[2]), "r"(a[3]), "r"(b[0]), "r"(b[1]));
}

// =====================================================================
// setup: transpose + hi/lo fp16 split of E -> blocked eB [t][ci][m][32]
// =====================================================================
__global__ void __launch_bounds__(256) esplit(const float* __restrict__ e) {
    __shared__ float tile[32][33];
    const int t = blockIdx.z;
    const int m0 = blockIdx.x * 32;
    const int n0 = blockIdx.y * 32;
    const int ci = n0 >> 5;
    const int tx = threadIdx.x & 31;
    const int ty = threadIdx.x >> 5;
    const float* eb = e + (size_t)t * NN * NN;
#pragma unroll
    for (int i = 0; i < 4; i++) {
        const int n = n0 + ty + i * 8;
        tile[ty + i * 8][tx] = eb[(size_t)n * NN + m0 + tx];
    }
    __syncthreads();
    const size_t rowbase = ((size_t)t * NCH + ci) * NN;
#pragma unroll
    for (int i = 0; i < 4; i++) {
        const int m = m0 + ty + i * 8;
        const float v = tile[tx][ty + i * 8];
        const __half hi = __float2half_rn(v);
        const __half lo = __float2half_rn(v - __half2float(hi));
        g_eB_hi[(rowbase + m) * 32 + tx] = hi;
        g_eB_lo[(rowbase + m) * 32 + tx] = lo;
    }
}

// per-iteration: transpose + split h -> blocked hB [ci][s][32]
__global__ void __launch_bounds__(256) hsplit(const int* __restrict__ iters, int it_idx) {
    if (it_idx >= *iters) return;
    __shared__ float tile[32][33];
    const int n0 = blockIdx.x * 32;
    const int ci = n0 >> 5;
    const int s0 = blockIdx.y * 32;
    const int tx = threadIdx.x & 31;
    const int ty = threadIdx.x >> 5;
#pragma unroll
    for (int i = 0; i < 4; i++) {
        const int n = n0 + ty + i * 8;
        tile[ty + i * 8][tx] = g_h[(size_t)n * SS + s0 + tx];
    }
    __syncthreads();
#pragma unroll
    for (int i = 0; i < 4; i++) {
        const int s = s0 + ty + i * 8;
        const float v = tile[tx][ty + i * 8];
        const __half hi = __float2half_rn(v);
        const __half lo = __float2half_rn(v - __half2float(hi));
        g_hB_hi[((size_t)ci * SS + s) * 32 + tx] = hi;
        g_hB_lo[((size_t)ci * SS + s) * 32 + tx] = lo;
    }
}

// =====================================================================
// K1 (HMMA): act[t,m,s] = sum_n e[t,n,m] * h[n,s] + ba[t,s]
// grid (32 m-tiles, 12 t), block 256 (8 warps: 4 m x 2 s).
// n-chunks of 32; 2-stage cp.async pipeline (48 KB/CTA -> multi-CTA/SM).
// Stage: Ahi 8K | Alo 8K | Bhi 4K | Blo 4K = 24 KB. Rows 64 B, SW64.
// =====================================================================
#define K1_STAGE 24576

__device__ __forceinline__ uint32_t sw64(int r, uint32_t c) {
    return (uint32_t)(r * 64) + (c ^ (uint32_t)((r & 6) << 3));
}

__device__ __forceinline__ void k1_load_chunk(int tid, int t, int m0, int ci, uint32_t smem) {
    const uint32_t base = smem + (uint32_t)(ci & 1) * K1_STAGE;
    const size_t arow = ((size_t)t * NCH + ci) * NN;   // blocked A chunk base
#pragma unroll
    for (int q = 0; q < 2; q++) {            // A: 128 rows x 4 x 16B, contiguous src
        const int idx = tid + 256 * q;
        const int r = idx >> 2, c16 = idx & 3;
        const int m = m0 + r;
        const int ok = (m < NN) ? 16 : 0;
        const int mc = (m < NN) ? m : (NN - 1);
        const uint32_t sw = sw64(r, (uint32_t)(c16 * 16));
        const size_t off = (arow + mc) * 32 + c16 * 8;
        cp16(base + sw,        g_eB_hi + off, ok);
        cp16(base + 8192 + sw, g_eB_lo + off, ok);
    }
    {                                        // B: 64 rows x 4 x 16B, contiguous src
        const int r = tid >> 2, c16 = tid & 3;
        const uint32_t sw = sw64(r, (uint32_t)(c16 * 16));
        const size_t off = ((size_t)ci * SS + r) * 32 + c16 * 8;
        cp16(base + 16384 + sw, g_hB_hi + off, 16);
        cp16(base + 20480 + sw, g_hB_lo + off, 16);
    }
    cp_commit();
}

__global__ void __launch_bounds__(256, 4) k1_hmma(const float* __restrict__ ba,
                                                  const int* __restrict__ iters, int it_idx) {
    if (it_idx >= *iters) return;
    extern __shared__ char dsm[];
    const int tid = threadIdx.x;
    const int wid = tid >> 5;
    const int lid = tid & 31;
    const int tt = blockIdx.y;
    const int m0 = blockIdx.x * 128;
    const uint32_t smem = smem_u32(dsm);

    const int wm = wid & 3;      // m32 block
    const int ws = wid >> 2;     // s32 block

    float acc[2][4][4];
#pragma unroll
    for (int a = 0; a < 2; a++)
#pragma unroll
        for (int b = 0; b < 4; b++)
#pragma unroll
            for (int j = 0; j < 4; j++) acc[a][b][j] = 0.f;

    const int arow = wm * 32 + (lid & 15);                      // + a*16
    const uint32_t abyt = (uint32_t)((lid >> 4) << 4);
    const int brow0 = ws * 32 + ((lid >> 4) << 3) + (lid & 7);  // + bp*16
    const uint32_t bbyt = (uint32_t)(((lid >> 3) & 1) << 4);

    k1_load_chunk(tid, tt, m0, 0, smem);

    for (int ci = 0; ci < NCH; ci++) {
        if (ci + 1 < NCH) { k1_load_chunk(tid, tt, m0, ci + 1, smem); cp_wait1(); }
        else cp_wait0();
        __syncthreads();

        const uint32_t base = smem + (uint32_t)(ci & 1) * K1_STAGE;
#pragma unroll
        for (int kk = 0; kk < 2; kk++) {
            const uint32_t kb = (uint32_t)(kk * 32);
            uint32_t ah[2][4], al[2][4], bh[2][4], bl[2][4];
#pragma unroll
            for (int a = 0; a < 2; a++) {
                const int r = arow + a * 16;
                const uint32_t ad = base + (uint32_t)(r * 64) + ((kb + abyt) ^ (uint32_t)((r & 6) << 3));
                ldsm4(ah[a][0], ah[a][1], ah[a][2], ah[a][3], ad);
                ldsm4(al[a][0], al[a][1], al[a][2], al[a][3], ad + 8192);
            }
#pragma unroll
            for (int bp = 0; bp < 2; bp++) {
                const int r = brow0 + bp * 16;
                const uint32_t bd = base + 16384 + (uint32_t)(r * 64) + ((kb + bbyt) ^ (uint32_t)((r & 6) << 3));
                ldsm4(bh[bp][0], bh[bp][1], bh[bp][2], bh[bp][3], bd);
                ldsm4(bl[bp][0], bl[bp][1], bl[bp][2], bl[bp][3], bd + 4096);
            }
#pragma unroll
            for (int a = 0; a < 2; a++)
#pragma unroll
                for (int b = 0; b < 4; b++) {
                    uint32_t bfh[2] = { bh[b >> 1][(b & 1) * 2], bh[b >> 1][(b & 1) * 2 + 1] };
                    uint32_t bfl[2] = { bl[b >> 1][(b & 1) * 2], bl[b >> 1][(b & 1) * 2 + 1] };
                    mma16816(acc[a][b], ah[a], bfh);   // Ehi*Hhi
                    mma16816(acc[a][b], al[a], bfh);   // Elo*Hhi
                    mma16816(acc[a][b], ah[a], bfl);   // Ehi*Hlo
                }
        }
        __syncthreads();   // protect stage ci before load of ci+2 next iter
    }

    // epilogue: add ba, store to g_act
#pragma unroll
    for (int b = 0; b < 4; b++) {
        const int scol = ws * 32 + b * 8 + (lid & 3) * 2;
        const float2 bav = *(const float2*)(ba + tt * SS + scol);
#pragma unroll
        for (int a = 0; a < 2; a++) {
            const int mrow = m0 + wm * 32 + a * 16 + (lid >> 2);
            if (mrow < NN) {
                float2 o = { acc[a][b][0] + bav.x, acc[a][b][1] + bav.y };
                *(float2*)&g_act[((size_t)tt * NN + mrow) * SS + scol] = o;
            }
            if (mrow + 8 < NN) {
                float2 o = { acc[a][b][2] + bav.x, acc[a][b][3] + bav.y };
                *(float2*)&g_act[((size_t)tt * NN + mrow + 8) * SS + scol] = o;
            }
        }
    }
}

// =====================================================================
// K2: aw[m,k] = sum_t sum_s act[t,m,s] * W[t,s,k] + T*bw[k]
// grid 125 (32 rows each), block 256.
// =====================================================================
__global__ void __launch_bounds__(256) k2_proj(const float* __restrict__ W,
                                               const float* __restrict__ bw,
                                               const int* __restrict__ iters,
                                               int it_idx) {
    if (it_idx >= *iters) return;
    __shared__ float sA[32][16];
    __shared__ float sW[16][192];

    const int m0 = blockIdx.x * 32;
    const int tid = threadIdx.x;
    const int lane = tid & 31;       // k0 = lane*6
    const int wrp = tid >> 5;        // 8 warps x 4 rows

    unsigned long long acc[4][3];
#pragma unroll
    for (int i = 0; i < 4; i++)
#pragma unroll
        for (int j = 0; j < 3; j++) acc[i][j] = 0ull;

    for (int t = 0; t < TT; t++) {
        for (int sb = 0; sb < SS; sb += 16) {
            __syncthreads();
            if (tid < 128) {     // act tile 32 x 16
                const int r = tid >> 2, c = (tid & 3) * 4;
                *(float4*)&sA[r][c] =
                    *(const float4*)(g_act + ((size_t)t * NN + m0 + r) * SS + sb + c);
            }
            {                    // W tile 16 x 192
                const int r = tid >> 4, c = tid & 15;
                const float* wr = W + ((size_t)t * SS + sb + r) * K3S;
#pragma unroll
                for (int k = 0; k < 3; k++)
                    *(float4*)&sW[r][4 * (c + 16 * k)] =
                        *(const float4*)(wr + 4 * (c + 16 * k));
            }
            __syncthreads();
#pragma unroll
            for (int s = 0; s < 16; s++) {
                const unsigned long long* wr =
                    (const unsigned long long*)&sW[s][lane * 6];
                const unsigned long long w0 = wr[0], w1 = wr[1], w2 = wr[2];
#pragma unroll
                for (int j = 0; j < 4; j++) {
                    const unsigned long long a2 = pack2(sA[wrp * 4 + j][s]);
                    ffma2(acc[j][0], a2, w0);
                    ffma2(acc[j][1], a2, w1);
                    ffma2(acc[j][2], a2, w2);
                }
            }
        }
    }
    const int k0 = lane * 6;
    float bwv[6];
#pragma unroll
    for (int p = 0; p < 6; p++) bwv[p] = 12.0f * bw[k0 + p];
#pragma unroll
    for (int j = 0; j < 4; j++) {
        const int m = m0 + wrp * 4 + j;
        float* dst = g_aw + (size_t)m * K3S + k0;
        dst[0] = lo32(acc[j][0]) + bwv[0];
        dst[1] = hi32(acc[j][0]) + bwv[1];
        dst[2] = lo32(acc[j][1]) + bwv[2];
        dst[3] = hi32(acc[j][1]) + bwv[3];
        dst[4] = lo32(acc[j][2]) + bwv[4];
        dst[5] = hi32(acc[j][2]) + bwv[5];
    }
}

// =====================================================================
// K34 (fused GRU update)
// =====================================================================
#define K34_SMEM ((8192 + 4096 + 1024 + 1024 + 1024) * 4)

__global__ void __launch_bounds__(256) k34_update(const float* __restrict__ uz_ur,
                                                  const float* __restrict__ uh,
                                                  const int* __restrict__ iters,
                                                  int it_idx) {
    if (it_idx >= *iters) return;
    extern __shared__ float sm[];
    float* sUZ = sm;                   // [64][128]
    float* sUH = sUZ + 64 * 128;       // [64][64]
    float* shh = sUH + 64 * 64;        // [16][64]
    float* srh = shh + 16 * 64;        // [16][64]
    float* sz  = srh + 16 * 64;        // [16][64]

    const int m0 = blockIdx.x * 16;
    const int tid = threadIdx.x;

#pragma unroll
    for (int i = 0; i < 8; i++)
        ((float4*)sUZ)[tid + 256 * i] = ((const float4*)uz_ur)[tid + 256 * i];
#pragma unroll
    for (int i = 0; i < 4; i++)
        ((float4*)sUH)[tid + 256 * i] = ((const float4*)uh)[tid + 256 * i];
    ((float4*)shh)[tid] = ((const float4*)(g_h + m0 * SS))[tid];
    __syncthreads();

    const int tx = tid & 15, ty = tid >> 4;
    const int m = m0 + ty;
    {   // gates
        const int k0 = tx * 8;
        float accv[8] = {0.f, 0.f, 0.f, 0.f, 0.f, 0.f, 0.f, 0.f};
#pragma unroll 8
        for (int s = 0; s < 64; s++) {
            const float hv = shh[ty * 64 + s];
#pragma unroll
            for (int j = 0; j < 8; j++) accv[j] += hv * sUZ[s * 128 + k0 + j];
        }
#pragma unroll
        for (int j = 0; j < 8; j++) {
            const int k = k0 + j;
            const float gt = g_aw[(size_t)m * K3S + k] + accv[j];
            const float sg = 1.0f / (1.0f + __expf(-gt));
            if (k < 64) sz[ty * 64 + k] = sg;
            else        srh[ty * 64 + (k - 64)] = sg * shh[ty * 64 + (k - 64)];
        }
    }
    __syncthreads();
    {   // candidate + update
        const int k0 = tx * 4;
        float accv[4] = {0.f, 0.f, 0.f, 0.f};
#pragma unroll 8
        for (int s = 0; s < 64; s++) {
            const float rv = srh[ty * 64 + s];
#pragma unroll
            for (int j = 0; j < 4; j++) accv[j] += rv * sUH[s * 64 + k0 + j];
        }
#pragma unroll
        for (int j = 0; j < 4; j++) {
            const int k = k0 + j;
            const float hhv = tanhf(g_aw[(size_t)m * K3S + 128 + k] + accv[j]);
            const float zv = sz[ty * 64 + k];
            const float hv = shh[ty * 64 + k];
            g_h[(size_t)m * SS + k] = (1.0f - zv) * hv + zv * hhv;
        }
    }
}

// ---- copies ----
__global__ void kcopy_in(const float* __restrict__ x) {
    const int i = blockIdx.x * 256 + threadIdx.x;
    if (i < NN * SS) g_h[i] = x[i];
}
__global__ void kcopy_out(float* __restrict__ out) {
    const int i = blockIdx.x * 256 + threadIdx.x;
    if (i < NN * SS) out[i] = g_h[i];
}

extern "C" void kernel_launch(void* const* d_in, const int* in_sizes, int n_in,
                              void* d_out, int out_size) {
    const float* x     = (const float*)d_in[0];
    const float* e     = (const float*)d_in[1];
    const float* ba    = (const float*)d_in[2];
    const float* bw    = (const float*)d_in[3];
    const float* W     = (const float*)d_in[4];
    const float* uz_ur = (const float*)d_in[5];
    const float* uh    = (const float*)d_in[6];
    const int*   iters = (const int*)d_in[7];
    float* out = (float*)d_out;

    cudaFuncSetAttribute(k1_hmma, cudaFuncAttributeMaxDynamicSharedMemorySize, 2 * K1_STAGE);
    cudaFuncSetAttribute(k1_hmma, cudaFuncAttributePreferredSharedMemoryCarveout, 100);
    cudaFuncSetAttribute(k34_update, cudaFuncAttributeMaxDynamicSharedMemorySize, K34_SMEM);

    const int cpb = (NN * SS + 255) / 256;
    kcopy_in<<<cpb, 256>>>(x);

    dim3 ge(NN / 32, NN / 32, TT);
    esplit<<<ge, 256>>>(e);

    const dim3 gh(NN / 32, SS / 32);
    const dim3 g1((NN + 127) / 128, TT);
    const int g2 = NN / 32;
    const int g34 = NN / 16;

    for (int it = 0; it < 10; it++) {
        hsplit<<<gh, 256>>>(iters, it);
        k1_hmma<<<g1, 256, 2 * K1_STAGE>>>(ba, iters, it);
        k2_proj<<<g2, 256>>>(W, bw, iters, it);
        k34_update<<<g34, 256, K34_SMEM>>>(uz_ur, uh, iters, it);
    }

    kcopy_out<<<cpb, 256>>>(out);
}

// round 10
// speedup vs baseline: 1.2541x; 1.2541x over previous
#include <cuda_runtime.h>
#include <cuda_fp16.h>
#include <cstdint>

#define NN 4000
#define SS 64
#define TT 12
#define K3S 192   // 3*SS
#define NCH 125   // 4000 / 32 n-chunks (k1)
#define KCH 24    // 768 / 32 k-chunks (k2)

// ------------------------- device scratch (no allocs) -------------------------
__device__ __align__(16) float g_h[NN * SS];
__device__ __align__(16) float g_aw[NN * K3S];
// act as fp16 hi/lo: [t][m][s]
__device__ __align__(16) __half g_act_hi[(size_t)TT * NN * SS];
__device__ __align__(16) __half g_act_lo[(size_t)TT * NN * SS];
// chunk-blocked E: [t][ci][m][32] halves
__device__ __align__(16) __half g_eB_hi[(size_t)TT * NCH * NN * 32];
__device__ __align__(16) __half g_eB_lo[(size_t)TT * NCH * NN * 32];
// chunk-blocked hT: [ci][s][32]
__device__ __align__(16) __half g_hB_hi[NCH * SS * 32];
__device__ __align__(16) __half g_hB_lo[NCH * SS * 32];
// W^T split: [n=192][k=768]
__device__ __align__(16) __half g_WT_hi[K3S * TT * SS];
__device__ __align__(16) __half g_WT_lo[K3S * TT * SS];

// ------------------------- helpers -------------------------
__device__ __forceinline__ uint32_t smem_u32(const void* p) {
    uint32_t a;
    asm("{ .reg .u64 t; cvta.to.shared.u64 t, %1; cvt.u32.u64 %0, t; }" : "=r"(a) : "l"(p));
    return a;
}
__device__ __forceinline__ void cp16(uint32_t dst, const void* src, int bytes) {
    asm volatile("cp.async.cg.shared.global [%0], [%1], 16, %2;" :: "r"(dst), "l"(src), "r"(bytes));
}
__device__ __forceinline__ void cp_commit() { asm volatile("cp.async.commit_group;"); }
__device__ __forceinline__ void cp_wait2()  { asm volatile("cp.async.wait_group 2;"); }
__device__ __forceinline__ void cp_wait1()  { asm volatile("cp.async.wait_group 1;"); }
__device__ __forceinline__ void cp_wait0()  { asm volatile("cp.async.wait_group 0;"); }

__device__ __forceinline__ void ldsm4(uint32_t& r0, uint32_t& r1, uint32_t& r2, uint32_t& r3,
                                      uint32_t addr) {
    asm volatile("ldmatrix.sync.aligned.m8n8.x4.shared.b16 {%0,%1,%2,%3}, [%4];"
                 : "=r"(r0), "=r"(r1), "=r"(r2), "=r"(r3) : "r"(addr));
}
__device__ __forceinline__ void mma16816(float* c, const uint32_t* a, const uint32_t* b) {
    asm volatile("mma.sync.aligned.m16n8k16.row.col.f32.f16.f16.f32 "
                 "{%0,%1,%2,%3}, {%4,%5,%6,%7}, {%8,%9}, {%0,%1,%2,%3};"
                 : "+f"(c[0]), "+f"(c[1]), "+f"(c[2]), "+f"(c[3])
                 : "r"(a[0]), "r"(a[1]), "r"(a[2]), "r"(a[3]), "r"(b[0]), "r"(b[1]));
}
__device__ __forceinline__ uint32_t sw64(int r, uint32_t c) {
    return (uint32_t)(r * 64) + (c ^ (uint32_t)((r & 6) << 3));
}
__device__ __forceinline__ uint32_t pack_h2(float a, float b) {
    __half2 h = __floats2half2_rn(a, b);
    return *(uint32_t*)&h;
}

#define K1_STAGE 24576   // A 8K+8K | B 4K+4K

// =====================================================================
// setup: transpose + hi/lo fp16 split of E -> blocked eB [t][ci][m][32]
// =====================================================================
__global__ void __launch_bounds__(256) esplit(const float* __restrict__ e) {
    __shared__ float tile[32][33];
    const int t = blockIdx.z;
    const int m0 = blockIdx.x * 32;
    const int n0 = blockIdx.y * 32;
    const int ci = n0 >> 5;
    const int tx = threadIdx.x & 31;
    const int ty = threadIdx.x >> 5;
    const float* eb = e + (size_t)t * NN * NN;
#pragma unroll
    for (int i = 0; i < 4; i++) {
        const int n = n0 + ty + i * 8;
        tile[ty + i * 8][tx] = eb[(size_t)n * NN + m0 + tx];
    }
    __syncthreads();
    const size_t rowbase = ((size_t)t * NCH + ci) * NN;
    const int px = threadIdx.x & 15;   // n-pair: 2px, 2px+1
    const int py = threadIdx.x >> 4;   // 16 m rows / pass
#pragma unroll
    for (int i = 0; i < 2; i++) {
        const int ml = py + 16 * i;
        const int m = m0 + ml;
        const float v0 = tile[2 * px][ml];
        const float v1 = tile[2 * px + 1][ml];
        const float h0 = __half2float(__float2half_rn(v0));
        const float h1 = __half2float(__float2half_rn(v1));
        const size_t o = (rowbase + m) * 32 + 2 * px;
        *(uint32_t*)&g_eB_hi[o] = pack_h2(v0, v1);
        *(uint32_t*)&g_eB_lo[o] = pack_h2(v0 - h0, v1 - h1);
    }
}

// one-time: W^T split  WT[n][k] = W[k/64][k%64][n],  n<192, k<768
__global__ void __launch_bounds__(256) wsplit(const float* __restrict__ W) {
    const int idx = blockIdx.x * 256 + threadIdx.x;   // n*768 + k
    if (idx >= K3S * TT * SS) return;
    const int n = idx / (TT * SS);
    const int k = idx - n * (TT * SS);
    const float v = W[(size_t)k * K3S + n];
    const __half hi = __float2half_rn(v);
    g_WT_hi[idx] = hi;
    g_WT_lo[idx] = __float2half_rn(v - __half2float(hi));
}

// per-iteration: transpose + split h -> blocked hB [ci][s][32]
__global__ void __launch_bounds__(256) hsplit(const int* __restrict__ iters, int it_idx) {
    if (it_idx >= *iters) return;
    __shared__ float tile[32][33];
    const int n0 = blockIdx.x * 32;
    const int ci = n0 >> 5;
    const int s0 = blockIdx.y * 32;
    const int tx = threadIdx.x & 31;
    const int ty = threadIdx.x >> 5;
#pragma unroll
    for (int i = 0; i < 4; i++) {
        const int n = n0 + ty + i * 8;
        tile[ty + i * 8][tx] = g_h[(size_t)n * SS + s0 + tx];
    }
    __syncthreads();
#pragma unroll
    for (int i = 0; i < 4; i++) {
        const int s = s0 + ty + i * 8;
        const float v = tile[tx][ty + i * 8];
        const __half hi = __float2half_rn(v);
        g_hB_hi[((size_t)ci * SS + s) * 32 + tx] = hi;
        g_hB_lo[((size_t)ci * SS + s) * 32 + tx] = __float2half_rn(v - __half2float(hi));
    }
}

// =====================================================================
// K1 (HMMA): act[t,m,s] = sum_n e[t,n,m] * h[n,s] + ba[t,s]  -> fp16 hi/lo
// grid (32 m-tiles, 12 t), block 256 (8 warps: 4 m x 2 s).
// 4-stage x 24KB pipeline, wait_group<=2, one barrier per chunk.
// =====================================================================
__device__ __forceinline__ void k1_load_chunk(int tid, int t, int m0, int ci, uint32_t smem) {
    const uint32_t base = smem + (uint32_t)(ci & 3) * K1_STAGE;
    const size_t arow = ((size_t)t * NCH + ci) * NN;
#pragma unroll
    for (int q = 0; q < 2; q++) {            // A: 128 rows x 4 x 16B
        const int idx = tid + 256 * q;
        const int r = idx >> 2, c16 = idx & 3;
        const int m = m0 + r;
        const int ok = (m < NN) ? 16 : 0;
        const int mc = (m < NN) ? m : (NN - 1);
        const uint32_t sw = sw64(r, (uint32_t)(c16 * 16));
        const size_t off = (arow + mc) * 32 + c16 * 8;
        cp16(base + sw,        g_eB_hi + off, ok);
        cp16(base + 8192 + sw, g_eB_lo + off, ok);
    }
    {                                        // B: 64 rows x 4 x 16B
        const int r = tid >> 2, c16 = tid & 3;
        const uint32_t sw = sw64(r, (uint32_t)(c16 * 16));
        const size_t off = ((size_t)ci * SS + r) * 32 + c16 * 8;
        cp16(base + 16384 + sw, g_hB_hi + off, 16);
        cp16(base + 20480 + sw, g_hB_lo + off, 16);
    }
    cp_commit();
}

__global__ void __launch_bounds__(256) k1_hmma(const float* __restrict__ ba,
                                               const int* __restrict__ iters, int it_idx) {
    if (it_idx >= *iters) return;
    extern __shared__ char dsm[];
    const int tid = threadIdx.x;
    const int wid = tid >> 5;
    const int lid = tid & 31;
    const int tt = blockIdx.y;
    const int m0 = blockIdx.x * 128;
    const uint32_t smem = smem_u32(dsm);

    const int wm = wid & 3;
    const int ws = wid >> 2;

    float acc[2][4][4];
#pragma unroll
    for (int a = 0; a < 2; a++)
#pragma unroll
        for (int b = 0; b < 4; b++)
#pragma unroll
            for (int j = 0; j < 4; j++) acc[a][b][j] = 0.f;

    const int arow = wm * 32 + (lid & 15);
    const uint32_t abyt = (uint32_t)((lid >> 4) << 4);
    const int brow0 = ws * 32 + ((lid >> 4) << 3) + (lid & 7);
    const uint32_t bbyt = (uint32_t)(((lid >> 3) & 1) << 4);

    k1_load_chunk(tid, tt, m0, 0, smem);
    k1_load_chunk(tid, tt, m0, 1, smem);
    k1_load_chunk(tid, tt, m0, 2, smem);

    for (int ci = 0; ci < NCH; ci++) {
        if (ci + 2 < NCH) cp_wait2();
        else if (ci + 1 < NCH) cp_wait1();
        else cp_wait0();
        __syncthreads();

        const uint32_t base = smem + (uint32_t)(ci & 3) * K1_STAGE;
#pragma unroll
        for (int kk = 0; kk < 2; kk++) {
            const uint32_t kb = (uint32_t)(kk * 32);
            uint32_t ah[2][4], al[2][4], bh[2][4], bl[2][4];
#pragma unroll
            for (int a = 0; a < 2; a++) {
                const int r = arow + a * 16;
                const uint32_t ad = base + (uint32_t)(r * 64) + ((kb + abyt) ^ (uint32_t)((r & 6) << 3));
                ldsm4(ah[a][0], ah[a][1], ah[a][2], ah[a][3], ad);
                ldsm4(al[a][0], al[a][1], al[a][2], al[a][3], ad + 8192);
            }
#pragma unroll
            for (int bp = 0; bp < 2; bp++) {
                const int r = brow0 + bp * 16;
                const uint32_t bd = base + 16384 + (uint32_t)(r * 64) + ((kb + bbyt) ^ (uint32_t)((r & 6) << 3));
                ldsm4(bh[bp][0], bh[bp][1], bh[bp][2], bh[bp][3], bd);
                ldsm4(bl[bp][0], bl[bp][1], bl[bp][2], bl[bp][3], bd + 4096);
            }
#pragma unroll
            for (int a = 0; a < 2; a++)
#pragma unroll
                for (int b = 0; b < 4; b++) {
                    uint32_t bfh[2] = { bh[b >> 1][(b & 1) * 2], bh[b >> 1][(b & 1) * 2 + 1] };
                    uint32_t bfl[2] = { bl[b >> 1][(b & 1) * 2], bl[b >> 1][(b & 1) * 2 + 1] };
                    mma16816(acc[a][b], ah[a], bfh);
                    mma16816(acc[a][b], al[a], bfh);
                    mma16816(acc[a][b], ah[a], bfl);
                }
        }
        if (ci + 3 < NCH) k1_load_chunk(tid, tt, m0, ci + 3, smem);
    }

    // epilogue: add ba, split to fp16 hi/lo, store
#pragma unroll
    for (int b = 0; b < 4; b++) {
        const int scol = ws * 32 + b * 8 + (lid & 3) * 2;
        const float2 bav = *(const float2*)(ba + tt * SS + scol);
#pragma unroll
        for (int a = 0; a < 2; a++) {
            const int mrow = m0 + wm * 32 + a * 16 + (lid >> 2);
#pragma unroll
            for (int half8 = 0; half8 < 2; half8++) {
                const int mr = mrow + half8 * 8;
                if (mr < NN) {
                    const float ox = acc[a][b][half8 * 2 + 0] + bav.x;
                    const float oy = acc[a][b][half8 * 2 + 1] + bav.y;
                    const float hx = __half2float(__float2half_rn(ox));
                    const float hy = __half2float(__float2half_rn(oy));
                    const size_t o = ((size_t)tt * NN + mr) * SS + scol;
                    *(uint32_t*)&g_act_hi[o] = pack_h2(ox, oy);
                    *(uint32_t*)&g_act_lo[o] = pack_h2(ox - hx, oy - hy);
                }
            }
        }
    }
}

// =====================================================================
// K2 (HMMA): aw[m,n] = sum_k act2[m][k] * WT[n][k] + 12*bw[n]
// k=(t*64+s), K=768. grid (32 m-tiles, 3 n-tiles of 64), block 256.
// Same tile machinery as k1; 4-stage pipeline over 24 chunks.
// =====================================================================
__device__ __forceinline__ void k2_load_chunk(int tid, int n0, int m0, int ci, uint32_t smem) {
    const uint32_t base = smem + (uint32_t)(ci & 3) * K1_STAGE;
    const int t = ci >> 1;
    const int sh = (ci & 1) * 32;
#pragma unroll
    for (int q = 0; q < 2; q++) {            // A: 128 rows(m) x 32 k
        const int idx = tid + 256 * q;
        const int r = idx >> 2, c16 = idx & 3;
        const int m = m0 + r;
        const int ok = (m < NN) ? 16 : 0;
        const int mc = (m < NN) ? m : (NN - 1);
        const uint32_t sw = sw64(r, (uint32_t)(c16 * 16));
        const size_t off = ((size_t)t * NN + mc) * SS + sh + c16 * 8;
        cp16(base + sw,        g_act_hi + off, ok);
        cp16(base + 8192 + sw, g_act_lo + off, ok);
    }
    {                                        // B: 64 rows(n) x 32 k
        const int r = tid >> 2, c16 = tid & 3;
        const uint32_t sw = sw64(r, (uint32_t)(c16 * 16));
        const size_t off = (size_t)(n0 + r) * (TT * SS) + t * SS + sh + c16 * 8;
        cp16(base + 16384 + sw, g_WT_hi + off, 16);
        cp16(base + 20480 + sw, g_WT_lo + off, 16);
    }
    cp_commit();
}

__global__ void __launch_bounds__(256) k2_hmma(const float* __restrict__ bw,
                                               const int* __restrict__ iters, int it_idx) {
    if (it_idx >= *iters) return;
    extern __shared__ char dsm[];
    const int tid = threadIdx.x;
    const int wid = tid >> 5;
    const int lid = tid & 31;
    const int n0 = blockIdx.y * 64;
    const int m0 = blockIdx.x * 128;
    const uint32_t smem = smem_u32(dsm);

    const int wm = wid & 3;
    const int wn = wid >> 2;

    float acc[2][4][4];
#pragma unroll
    for (int a = 0; a < 2; a++)
#pragma unroll
        for (int b = 0; b < 4; b++)
#pragma unroll
            for (int j = 0; j < 4; j++) acc[a][b][j] = 0.f;

    const int arow = wm * 32 + (lid & 15);
    const uint32_t abyt = (uint32_t)((lid >> 4) << 4);
    const int brow0 = wn * 32 + ((lid >> 4) << 3) + (lid & 7);
    const uint32_t bbyt = (uint32_t)(((lid >> 3) & 1) << 4);

    k2_load_chunk(tid, n0, m0, 0, smem);
    k2_load_chunk(tid, n0, m0, 1, smem);
    k2_load_chunk(tid, n0, m0, 2, smem);

    for (int ci = 0; ci < KCH; ci++) {
        if (ci + 2 < KCH) cp_wait2();
        else if (ci + 1 < KCH) cp_wait1();
        else cp_wait0();
        __syncthreads();

        const uint32_t base = smem + (uint32_t)(ci & 3) * K1_STAGE;
#pragma unroll
        for (int kk = 0; kk < 2; kk++) {
            const uint32_t kb = (uint32_t)(kk * 32);
            uint32_t ah[2][4], al[2][4], bh[2][4], bl[2][4];
#pragma unroll
            for (int a = 0; a < 2; a++) {
                const int r = arow + a * 16;
                const uint32_t ad = base + (uint32_t)(r * 64) + ((kb + abyt) ^ (uint32_t)((r & 6) << 3));
                ldsm4(ah[a][0], ah[a][1], ah[a][2], ah[a][3], ad);
                ldsm4(al[a][0], al[a][1], al[a][2], al[a][3], ad + 8192);
            }
#pragma unroll
            for (int bp = 0; bp < 2; bp++) {
                const int r = brow0 + bp * 16;
                const uint32_t bd = base + 16384 + (uint32_t)(r * 64) + ((kb + bbyt) ^ (uint32_t)((r & 6) << 3));
                ldsm4(bh[bp][0], bh[bp][1], bh[bp][2], bh[bp][3], bd);
                ldsm4(bl[bp][0], bl[bp][1], bl[bp][2], bl[bp][3], bd + 4096);
            }
#pragma unroll
            for (int a = 0; a < 2; a++)
#pragma unroll
                for (int b = 0; b < 4; b++) {
                    uint32_t bfh[2] = { bh[b >> 1][(b & 1) * 2], bh[b >> 1][(b & 1) * 2 + 1] };
                    uint32_t bfl[2] = { bl[b >> 1][(b & 1) * 2], bl[b >> 1][(b & 1) * 2 + 1] };
                    mma16816(acc[a][b], ah[a], bfh);
                    mma16816(acc[a][b], al[a], bfh);
                    mma16816(acc[a][b], ah[a], bfl);
                }
        }
        if (ci + 3 < KCH) k2_load_chunk(tid, n0, m0, ci + 3, smem);
    }

    // epilogue: + 12*bw, store fp32 g_aw
#pragma unroll
    for (int b = 0; b < 4; b++) {
        const int ncol = n0 + wn * 32 + b * 8 + (lid & 3) * 2;
        const float2 bwv = *(const float2*)(bw + ncol);
#pragma unroll
        for (int a = 0; a < 2; a++) {
            const int mrow = m0 + wm * 32 + a * 16 + (lid >> 2);
            if (mrow < NN) {
                float2 o = { acc[a][b][0] + 12.0f * bwv.x, acc[a][b][1] + 12.0f * bwv.y };
                *(float2*)&g_aw[(size_t)mrow * K3S + ncol] = o;
            }
            if (mrow + 8 < NN) {
                float2 o = { acc[a][b][2] + 12.0f * bwv.x, acc[a][b][3] + 12.0f * bwv.y };
                *(float2*)&g_aw[(size_t)(mrow + 8) * K3S + ncol] = o;
            }
        }
    }
}

// =====================================================================
// K34 (fused GRU update)
// =====================================================================
#define K34_SMEM ((8192 + 4096 + 1024 + 1024 + 1024) * 4)

__global__ void __launch_bounds__(256) k34_update(const float* __restrict__ uz_ur,
                                                  const float* __restrict__ uh,
                                                  const int* __restrict__ iters,
                                                  int it_idx) {
    if (it_idx >= *iters) return;
    extern __shared__ float sm[];
    float* sUZ = sm;
    float* sUH = sUZ + 64 * 128;
    float* shh = sUH + 64 * 64;
    float* srh = shh + 16 * 64;
    float* sz  = srh + 16 * 64;

    const int m0 = blockIdx.x * 16;
    const int tid = threadIdx.x;

#pragma unroll
    for (int i = 0; i < 8; i++)
        ((float4*)sUZ)[tid + 256 * i] = ((const float4*)uz_ur)[tid + 256 * i];
#pragma unroll
    for (int i = 0; i < 4; i++)
        ((float4*)sUH)[tid + 256 * i] = ((const float4*)uh)[tid + 256 * i];
    ((float4*)shh)[tid] = ((const float4*)(g_h + m0 * SS))[tid];
    __syncthreads();

    const int tx = tid & 15, ty = tid >> 4;
    const int m = m0 + ty;
    {
        const int k0 = tx * 8;
        float accv[8] = {0.f, 0.f, 0.f, 0.f, 0.f, 0.f, 0.f, 0.f};
#pragma unroll 8
        for (int s = 0; s < 64; s++) {
            const float hv = shh[ty * 64 + s];
#pragma unroll
            for (int j = 0; j < 8; j++) accv[j] += hv * sUZ[s * 128 + k0 + j];
        }
#pragma unroll
        for (int j = 0; j < 8; j++) {
            const int k = k0 + j;
            const float gt = g_aw[(size_t)m * K3S + k] + accv[j];
            const float sg = 1.0f / (1.0f + __expf(-gt));
            if (k < 64) sz[ty * 64 + k] = sg;
            else        srh[ty * 64 + (k - 64)] = sg * shh[ty * 64 + (k - 64)];
        }
    }
    __syncthreads();
    {
        const int k0 = tx * 4;
        float accv[4] = {0.f, 0.f, 0.f, 0.f};
#pragma unroll 8
        for (int s = 0; s < 64; s++) {
            const float rv = srh[ty * 64 + s];
#pragma unroll
            for (int j = 0; j < 4; j++) accv[j] += rv * sUH[s * 64 + k0 + j];
        }
#pragma unroll
        for (int j = 0; j < 4; j++) {
            const int k = k0 + j;
            const float hhv = tanhf(g_aw[(size_t)m * K3S + 128 + k] + accv[j]);
            const float zv = sz[ty * 64 + k];
            const float hv = shh[ty * 64 + k];
            g_h[(size_t)m * SS + k] = (1.0f - zv) * hv + zv * hhv;
        }
    }
}

// ---- copies ----
__global__ void kcopy_in(const float* __restrict__ x) {
    const int i = blockIdx.x * 256 + threadIdx.x;
    if (i < NN * SS) g_h[i] = x[i];
}
__global__ void kcopy_out(float* __restrict__ out) {
    const int i = blockIdx.x * 256 + threadIdx.x;
    if (i < NN * SS) out[i] = g_h[i];
}

extern "C" void kernel_launch(void* const* d_in, const int* in_sizes, int n_in,
                              void* d_out, int out_size) {
    const float* x     = (const float*)d_in[0];
    const float* e     = (const float*)d_in[1];
    const float* ba    = (const float*)d_in[2];
    const float* bw    = (const float*)d_in[3];
    const float* W     = (const float*)d_in[4];
    const float* uz_ur = (const float*)d_in[5];
    const float* uh    = (const float*)d_in[6];
    const int*   iters = (const int*)d_in[7];
    float* out = (float*)d_out;

    cudaFuncSetAttribute(k1_hmma, cudaFuncAttributeMaxDynamicSharedMemorySize, 4 * K1_STAGE);
    cudaFuncSetAttribute(k1_hmma, cudaFuncAttributePreferredSharedMemoryCarveout, 100);
    cudaFuncSetAttribute(k2_hmma, cudaFuncAttributeMaxDynamicSharedMemorySize, 4 * K1_STAGE);
    cudaFuncSetAttribute(k2_hmma, cudaFuncAttributePreferredSharedMemoryCarveout, 100);
    cudaFuncSetAttribute(k34_update, cudaFuncAttributeMaxDynamicSharedMemorySize, K34_SMEM);

    const int cpb = (NN * SS + 255) / 256;
    kcopy_in<<<cpb, 256>>>(x);

    dim3 ge(NN / 32, NN / 32, TT);
    esplit<<<ge, 256>>>(e);
    wsplit<<<(K3S * TT * SS + 255) / 256, 256>>>(W);

    const dim3 gh(NN / 32, SS / 32);
    const dim3 g1((NN + 127) / 128, TT);
    const dim3 g2((NN + 127) / 128, 3);
    const int g34 = NN / 16;

    for (int it = 0; it < 10; it++) {
        hsplit<<<gh, 256>>>(iters, it);
        k1_hmma<<<g1, 256, 4 * K1_STAGE>>>(ba, iters, it);
        k2_hmma<<<g2, 256, 4 * K1_STAGE>>>(bw, iters, it);
        k34_update<<<g34, 256, K34_SMEM>>>(uz_ur, uh, iters, it);
    }

    kcopy_out<<<cpb, 256>>>(out);
}